// round 4
// baseline (speedup 1.0000x reference)
#include <cuda_runtime.h>
#include <stdint.h>

#define D        128
#define BM       64
#define BK       32
#define MAXN     50000

// Scratch for support = x @ W  (50000 x 128 f32 = 25.6 MB)
__device__ float g_support[(size_t)MAXN * D];

// ---------------------------------------------------------------------------
// Kernel 1: out[n][d] = bias[d]   (float4 vectorized)
// ---------------------------------------------------------------------------
__global__ void init_out_kernel(const float4* __restrict__ bias4,
                                float4* __restrict__ out4, int n4) {
    int i = blockIdx.x * blockDim.x + threadIdx.x;
    if (i < n4) out4[i] = bias4[i & 31];   // row = 32 float4
}

// ---------------------------------------------------------------------------
// Kernel 2: support = x @ W      fp32 register-tiled GEMM
//   BM=64 rows/block, full N=128, BK=32 k-tile, 128 threads, 8x8 per thread
// ---------------------------------------------------------------------------
__global__ __launch_bounds__(128) void gemm_kernel(
    const float* __restrict__ A,   // [M, 128]
    const float* __restrict__ W,   // [128, 128]
    int M)
{
    __shared__ float As[BM][BK + 4];
    __shared__ float Bs[BK][D];

    const int tid = threadIdx.x;
    const int tx  = tid & 15;          // col group (8 cols each)
    const int ty  = tid >> 4;          // row group (8 rows each)
    const int row0 = blockIdx.x * BM;

    float acc[8][8];
#pragma unroll
    for (int i = 0; i < 8; ++i)
#pragma unroll
        for (int j = 0; j < 8; ++j) acc[i][j] = 0.f;

    for (int kt = 0; kt < D; kt += BK) {
        // load A tile [BM][BK]  (512 float4, 4 per thread)
#pragma unroll
        for (int p = tid; p < BM * BK / 4; p += 128) {
            int m  = p >> 3;           // 8 float4 per row
            int k4 = p & 7;
            float4 v = make_float4(0.f, 0.f, 0.f, 0.f);
            int gr = row0 + m;
            if (gr < M)
                v = *(const float4*)&A[(size_t)gr * D + kt + k4 * 4];
            *(float4*)&As[m][k4 * 4] = v;
        }
        // load B tile [BK][D]  (1024 float4, 8 per thread)
#pragma unroll
        for (int p = tid; p < BK * D / 4; p += 128) {
            int kk = p >> 5;           // 32 float4 per row
            int c4 = p & 31;
            *(float4*)&Bs[kk][c4 * 4] =
                *(const float4*)&W[(size_t)(kt + kk) * D + c4 * 4];
        }
        __syncthreads();

#pragma unroll
        for (int k = 0; k < BK; ++k) {
            float a[8];
#pragma unroll
            for (int i = 0; i < 8; ++i) a[i] = As[ty * 8 + i][k];
            float4 b0 = *(float4*)&Bs[k][tx * 8];
            float4 b1 = *(float4*)&Bs[k][tx * 8 + 4];
            float b[8] = {b0.x, b0.y, b0.z, b0.w, b1.x, b1.y, b1.z, b1.w};
#pragma unroll
            for (int i = 0; i < 8; ++i)
#pragma unroll
                for (int j = 0; j < 8; ++j)
                    acc[i][j] = fmaf(a[i], b[j], acc[i][j]);
        }
        __syncthreads();
    }

#pragma unroll
    for (int i = 0; i < 8; ++i) {
        int gr = row0 + ty * 8 + i;
        if (gr < M) {
            *(float4*)&g_support[(size_t)gr * D + tx * 8] =
                make_float4(acc[i][0], acc[i][1], acc[i][2], acc[i][3]);
            *(float4*)&g_support[(size_t)gr * D + tx * 8 + 4] =
                make_float4(acc[i][4], acc[i][5], acc[i][6], acc[i][7]);
        }
    }
}

// ---------------------------------------------------------------------------
// Kernel 3: scatter-add. One warp per edge, one float4 per lane.
//   out[row] += support[col] * w      via red.global.add.v4.f32 (no-return)
//   NOTE: edge indices are int32 (JAX x64-disabled downcasts int64 -> int32).
// ---------------------------------------------------------------------------
__global__ void scatter_kernel(const float* __restrict__ ew,
                               const int* __restrict__ er,
                               const int* __restrict__ ec,
                               float* __restrict__ out, int n_edges)
{
    int g    = blockIdx.x * blockDim.x + threadIdx.x;
    int e    = g >> 5;
    int lane = g & 31;
    if (e >= n_edges) return;

    int   r = er[e];
    int   c = ec[e];
    float w = ew[e];

    const float4* sup4 = (const float4*)g_support;
    float4 v = sup4[(size_t)c * (D / 4) + lane];
    float* dst = out + (size_t)r * D + lane * 4;

    asm volatile("red.global.add.v4.f32 [%0], {%1, %2, %3, %4};"
                 :: "l"(dst), "f"(v.x * w), "f"(v.y * w),
                    "f"(v.z * w), "f"(v.w * w)
                 : "memory");
}

// ---------------------------------------------------------------------------
extern "C" void kernel_launch(void* const* d_in, const int* in_sizes, int n_in,
                              void* d_out, int out_size)
{
    const float* x      = (const float*)d_in[0];   // [N, 128]
    const float* weight = (const float*)d_in[1];   // [128, 128]
    const float* bias   = (const float*)d_in[2];   // [128]
    const float* ew     = (const float*)d_in[3];   // [E]
    const int*   er     = (const int*)d_in[4];     // [E] int32 (JAX downcast)
    const int*   ec     = (const int*)d_in[5];     // [E] int32
    float*       out    = (float*)d_out;           // [N, 128]

    const int M = in_sizes[0] / D;        // 50000
    const int E = in_sizes[3];            // 800000

    // 1) out = bias (broadcast)
    {
        int n4 = out_size / 4;
        int blocks = (n4 + 255) / 256;
        init_out_kernel<<<blocks, 256>>>((const float4*)bias, (float4*)out, n4);
    }
    // 2) support = x @ W
    {
        int blocks = (M + BM - 1) / BM;
        gemm_kernel<<<blocks, 128>>>(x, weight, M);
    }
    // 3) scatter-add edges
    {
        long long threads = (long long)E * 32;
        int blocks = (int)((threads + 255) / 256);
        scatter_kernel<<<blocks, 256>>>(ew, er, ec, out, E);
    }
}

// round 5
// speedup vs baseline: 1.9522x; 1.9522x over previous
#include <cuda_runtime.h>
#include <stdint.h>

typedef unsigned long long ull;

#define D        128
#define BM       64
#define BK       32
#define MAXN     50000
#define MAXE     800000
#define SCAN_B   1024                       // nodes per scan block

// ---- scratch (__device__ globals; no allocations allowed) ----
__device__ float g_support[(size_t)MAXN * D];     // x @ W        (25.6 MB)
__device__ int   g_deg[MAXN];                     // degree histogram
__device__ int   g_start[MAXN + 1];               // CSR row offsets
__device__ int   g_pos[MAXN];                     // fill cursors
__device__ ull   g_edge[MAXE];                    // packed (col, weight_bits)
__device__ int   g_bsum[(MAXN + SCAN_B - 1) / SCAN_B]; // per-block sums
__device__ int   g_boff[(MAXN + SCAN_B - 1) / SCAN_B]; // per-block offsets

// ---------------------------------------------------------------------------
// packed f32x2 helpers (sm_103a FFMA2 — PTX-only, ptxas won't auto-fuse)
// ---------------------------------------------------------------------------
__device__ __forceinline__ void ffma2(ull& d, ull a, ull b) {
    asm("fma.rn.f32x2 %0, %1, %2, %0;" : "+l"(d) : "l"(a), "l"(b));
}
__device__ __forceinline__ ull pk2(float lo, float hi) {
    ull r; asm("mov.b64 %0, {%1, %2};" : "=l"(r) : "f"(lo), "f"(hi)); return r;
}
__device__ __forceinline__ void upk2(ull v, float& lo, float& hi) {
    asm("mov.b64 {%0, %1}, %2;" : "=f"(lo), "=f"(hi) : "l"(v));
}

// ---------------------------------------------------------------------------
// CSR build
// ---------------------------------------------------------------------------
__global__ void zero_deg_kernel(int M) {
    int i = blockIdx.x * blockDim.x + threadIdx.x;
    if (i < M) g_deg[i] = 0;
}

__global__ void hist_kernel(const int* __restrict__ er, int E) {
    int i = blockIdx.x * blockDim.x + threadIdx.x;
    if (i < E) atomicAdd(&g_deg[er[i]], 1);
}

// K1: per-block exclusive scan of degrees; block totals to g_bsum
__global__ __launch_bounds__(SCAN_B) void scan1_kernel(int M) {
    __shared__ int sh[SCAN_B];
    int i = blockIdx.x * SCAN_B + threadIdx.x;
    int v = (i < M) ? g_deg[i] : 0;
    sh[threadIdx.x] = v;
    __syncthreads();
    // Hillis-Steele inclusive scan
#pragma unroll
    for (int off = 1; off < SCAN_B; off <<= 1) {
        int t = (threadIdx.x >= off) ? sh[threadIdx.x - off] : 0;
        __syncthreads();
        sh[threadIdx.x] += t;
        __syncthreads();
    }
    if (i < M) g_start[i] = sh[threadIdx.x] - v;   // exclusive, block-local
    if (threadIdx.x == SCAN_B - 1) g_bsum[blockIdx.x] = sh[SCAN_B - 1];
}

// K2: scan the (<=49) block sums; write grand total to g_start[M]
__global__ void scan2_kernel(int nb, int M) {
    __shared__ int sh[64];
    if (threadIdx.x < nb) sh[threadIdx.x] = g_bsum[threadIdx.x];
    __syncthreads();
    if (threadIdx.x == 0) {
        int run = 0;
        for (int b = 0; b < nb; ++b) { int t = sh[b]; sh[b] = run; run += t; }
        g_start[M] = run;
    }
    __syncthreads();
    if (threadIdx.x < nb) g_boff[threadIdx.x] = sh[threadIdx.x];
}

// K3: add block offsets, init cursors
__global__ __launch_bounds__(SCAN_B) void scan3_kernel(int M) {
    int i = blockIdx.x * SCAN_B + threadIdx.x;
    if (i < M) {
        int s = g_start[i] + g_boff[blockIdx.x];
        g_start[i] = s;
        g_pos[i]   = s;
    }
}

// reorder edges into CSR slots, packing (col, weight) into 8 bytes
__global__ void reorder_kernel(const float* __restrict__ ew,
                               const int* __restrict__ er,
                               const int* __restrict__ ec, int E) {
    int e = blockIdx.x * blockDim.x + threadIdx.x;
    if (e >= E) return;
    int p = atomicAdd(&g_pos[er[e]], 1);
    g_edge[p] = ((ull)__float_as_uint(ew[e]) << 32) | (unsigned)ec[e];
}

// ---------------------------------------------------------------------------
// GEMM: support = x @ W   (fp32, packed f32x2 inner product)
//   BM=64 rows/block, full N=128, BK=32, 128 threads, 8 rows x 8 cols each
// ---------------------------------------------------------------------------
__global__ __launch_bounds__(128) void gemm_kernel(
    const float* __restrict__ A, const float* __restrict__ W, int M)
{
    __shared__ float As[BM][BK + 4];
    __shared__ float Bs[BK][D];

    const int tid  = threadIdx.x;
    const int tx   = tid & 15;          // col group (8 cols)
    const int ty   = tid >> 4;          // row group (8 rows)
    const int row0 = blockIdx.x * BM;

    ull accP[8][4];
#pragma unroll
    for (int i = 0; i < 8; ++i)
#pragma unroll
        for (int j = 0; j < 4; ++j) accP[i][j] = 0ull;

    for (int kt = 0; kt < D; kt += BK) {
#pragma unroll
        for (int p = tid; p < BM * BK / 4; p += 128) {
            int m = p >> 3, k4 = p & 7;
            float4 v = make_float4(0.f, 0.f, 0.f, 0.f);
            int gr = row0 + m;
            if (gr < M) v = *(const float4*)&A[(size_t)gr * D + kt + k4 * 4];
            *(float4*)&As[m][k4 * 4] = v;
        }
#pragma unroll
        for (int p = tid; p < BK * D / 4; p += 128) {
            int kk = p >> 5, c4 = p & 31;
            *(float4*)&Bs[kk][c4 * 4] =
                *(const float4*)&W[(size_t)(kt + kk) * D + c4 * 4];
        }
        __syncthreads();

#pragma unroll
        for (int k = 0; k < BK; ++k) {
            ull aP[8];
#pragma unroll
            for (int i = 0; i < 8; ++i) {
                float a = As[ty * 8 + i][k];
                aP[i] = pk2(a, a);
            }
            const ull* bp = (const ull*)&Bs[k][tx * 8];   // 32B-aligned
            ull bP[4] = {bp[0], bp[1], bp[2], bp[3]};
#pragma unroll
            for (int i = 0; i < 8; ++i)
#pragma unroll
                for (int j = 0; j < 4; ++j)
                    ffma2(accP[i][j], aP[i], bP[j]);
        }
        __syncthreads();
    }

#pragma unroll
    for (int i = 0; i < 8; ++i) {
        int gr = row0 + ty * 8 + i;
        if (gr < M) {
            float c0, c1, c2, c3, c4, c5, c6, c7;
            upk2(accP[i][0], c0, c1); upk2(accP[i][1], c2, c3);
            upk2(accP[i][2], c4, c5); upk2(accP[i][3], c6, c7);
            *(float4*)&g_support[(size_t)gr * D + tx * 8]     = make_float4(c0, c1, c2, c3);
            *(float4*)&g_support[(size_t)gr * D + tx * 8 + 4] = make_float4(c4, c5, c6, c7);
        }
    }
}

// ---------------------------------------------------------------------------
// Gather: one warp per node. out[r] = bias + sum_e w_e * support[col_e]
// Atomic-free: each output row written exactly once.
// ---------------------------------------------------------------------------
__global__ __launch_bounds__(256) void gather_kernel(
    const float4* __restrict__ bias4, float4* __restrict__ out4, int M)
{
    int warp = (blockIdx.x * blockDim.x + threadIdx.x) >> 5;
    int lane = threadIdx.x & 31;
    if (warp >= M) return;

    int s = g_start[warp];
    int e = g_start[warp + 1];

    const float4* sup4 = (const float4*)g_support;
    float4 acc = make_float4(0.f, 0.f, 0.f, 0.f);

    int i = s;
    // unrolled-by-2 for load-level parallelism
    for (; i + 1 < e; i += 2) {
        ull p0 = g_edge[i], p1 = g_edge[i + 1];
        int   c0 = (int)(unsigned)p0,        c1 = (int)(unsigned)p1;
        float w0 = __uint_as_float((unsigned)(p0 >> 32));
        float w1 = __uint_as_float((unsigned)(p1 >> 32));
        float4 v0 = sup4[(size_t)c0 * (D / 4) + lane];
        float4 v1 = sup4[(size_t)c1 * (D / 4) + lane];
        acc.x = fmaf(v0.x, w0, acc.x); acc.y = fmaf(v0.y, w0, acc.y);
        acc.z = fmaf(v0.z, w0, acc.z); acc.w = fmaf(v0.w, w0, acc.w);
        acc.x = fmaf(v1.x, w1, acc.x); acc.y = fmaf(v1.y, w1, acc.y);
        acc.z = fmaf(v1.z, w1, acc.z); acc.w = fmaf(v1.w, w1, acc.w);
    }
    if (i < e) {
        ull p0 = g_edge[i];
        int   c0 = (int)(unsigned)p0;
        float w0 = __uint_as_float((unsigned)(p0 >> 32));
        float4 v0 = sup4[(size_t)c0 * (D / 4) + lane];
        acc.x = fmaf(v0.x, w0, acc.x); acc.y = fmaf(v0.y, w0, acc.y);
        acc.z = fmaf(v0.z, w0, acc.z); acc.w = fmaf(v0.w, w0, acc.w);
    }

    float4 b = bias4[lane];
    acc.x += b.x; acc.y += b.y; acc.z += b.z; acc.w += b.w;
    out4[(size_t)warp * (D / 4) + lane] = acc;
}

// ---------------------------------------------------------------------------
extern "C" void kernel_launch(void* const* d_in, const int* in_sizes, int n_in,
                              void* d_out, int out_size)
{
    const float* x      = (const float*)d_in[0];   // [N, 128]
    const float* weight = (const float*)d_in[1];   // [128, 128]
    const float* bias   = (const float*)d_in[2];   // [128]
    const float* ew     = (const float*)d_in[3];   // [E]
    const int*   er     = (const int*)d_in[4];     // [E] int32
    const int*   ec     = (const int*)d_in[5];     // [E] int32
    float*       out    = (float*)d_out;           // [N, 128]

    const int M  = in_sizes[0] / D;                // 50000
    const int E  = in_sizes[3];                    // 800000
    const int NB = (M + SCAN_B - 1) / SCAN_B;      // scan blocks (49)

    // --- CSR build ---
    zero_deg_kernel<<<(M + 255) / 256, 256>>>(M);
    hist_kernel<<<(E + 255) / 256, 256>>>(er, E);
    scan1_kernel<<<NB, SCAN_B>>>(M);
    scan2_kernel<<<1, 64>>>(NB, M);
    scan3_kernel<<<NB, SCAN_B>>>(M);
    reorder_kernel<<<(E + 255) / 256, 256>>>(ew, er, ec, E);

    // --- support = x @ W ---
    gemm_kernel<<<(M + BM - 1) / BM, 128>>>(x, weight, M);

    // --- out = bias + CSR-gather ---
    {
        long long threads = (long long)M * 32;
        gather_kernel<<<(int)((threads + 255) / 256), 256>>>(
            (const float4*)bias, (float4*)out, M);
    }
}